// round 8
// baseline (speedup 1.0000x reference)
#include <cuda_runtime.h>
#include <cuda_fp16.h>
#include <cstdint>

// ---------------- problem dims ----------------
#define BB   2
#define LL   4096
#define DD   768
#define HH   12
#define HDD  64
#define NBB  64
#define MLPD 3072
#define ROWS (BB*LL)      // 8192
#define QKVD (3*DD)       // 2304
#define EPSV 1e-6f

// ---------------- scratch (device globals; no allocation allowed) ------------
__device__ float g_h  [ROWS*DD];
__device__ float g_qkv[ROWS*QKVD];
__device__ float g_ctx[ROWS*DD];
__device__ float g_x1 [ROWS*DD];
__device__ float g_y  [ROWS*DD];
__device__ float g_z  [ROWS*MLPD];
// transposed (K-major) weights, pre-converted to half
__device__ __half g_wqkvt[QKVD*DD];   // rows: [Wq^T ; Wk^T ; Wv^T]
__device__ __half g_wot[DD*DD];
__device__ __half g_w1t[MLPD*DD];
__device__ __half g_w2t[DD*MLPD];

// =====================================================================
// helpers
// =====================================================================
__device__ __forceinline__ uint32_t smem_u32(const void* p) {
    uint32_t a;
    asm("{ .reg .u64 t; cvta.to.shared.u64 t, %1; cvt.u32.u64 %0, t; }" : "=r"(a) : "l"(p));
    return a;
}

__device__ __forceinline__ void mma16(float* d, const uint32_t* a, const uint32_t* b) {
    asm volatile(
        "mma.sync.aligned.m16n8k16.row.col.f32.f16.f16.f32 "
        "{%0,%1,%2,%3}, {%4,%5,%6,%7}, {%8,%9}, {%0,%1,%2,%3};"
        : "+f"(d[0]), "+f"(d[1]), "+f"(d[2]), "+f"(d[3])
        : "r"(a[0]), "r"(a[1]), "r"(a[2]), "r"(a[3]), "r"(b[0]), "r"(b[1]));
}

__device__ __forceinline__ void ldsm4(uint32_t* r, uint32_t addr) {
    asm volatile("ldmatrix.sync.aligned.m8n8.x4.shared.b16 {%0,%1,%2,%3}, [%4];"
        : "=r"(r[0]), "=r"(r[1]), "=r"(r[2]), "=r"(r[3]) : "r"(addr));
}

__device__ __forceinline__ uint32_t pack_h2(float lo, float hi) {
    __half2 h = __floats2half2_rn(lo, hi);    // .x = lo, .y = hi
    return *reinterpret_cast<uint32_t*>(&h);
}

// =====================================================================
// transpose (fp32 in -> half out): out[C,R] = half(in[R,C]^T)
// =====================================================================
__global__ __launch_bounds__(256) void transpose_h_kernel(
    const float* __restrict__ in, __half* __restrict__ out, int R, int C)
{
    __shared__ float t[32][33];
    int c0 = blockIdx.x * 32, r0 = blockIdx.y * 32;
    int x = threadIdx.x, y = threadIdx.y;
    #pragma unroll
    for (int i = 0; i < 32; i += 8)
        t[y + i][x] = in[(size_t)(r0 + y + i) * C + c0 + x];
    __syncthreads();
    #pragma unroll
    for (int i = 0; i < 32; i += 8)
        out[(size_t)(c0 + y + i) * R + r0 + x] = __float2half(t[x][y + i]);
}

// batched 3-matrix transpose (Wq, Wk, Wv -> slices of g_wqkvt), each DD x DD
__global__ __launch_bounds__(256) void transpose3_h_kernel(
    const float* __restrict__ s0, const float* __restrict__ s1,
    const float* __restrict__ s2, __half* __restrict__ out)
{
    __shared__ float t[32][33];
    const float* in = (blockIdx.z == 0) ? s0 : (blockIdx.z == 1) ? s1 : s2;
    __half* o = out + (size_t)blockIdx.z * DD * DD;
    int c0 = blockIdx.x * 32, r0 = blockIdx.y * 32;
    int x = threadIdx.x, y = threadIdx.y;
    #pragma unroll
    for (int i = 0; i < 32; i += 8)
        t[y + i][x] = in[(size_t)(r0 + y + i) * DD + c0 + x];
    __syncthreads();
    #pragma unroll
    for (int i = 0; i < 32; i += 8)
        o[(size_t)(c0 + y + i) * DD + r0 + x] = __float2half(t[x][y + i]);
}

// =====================================================================
// LayerNorm: one block (256 thr) per row, D=768 = 3 elems/thread
// =====================================================================
__global__ __launch_bounds__(256) void layernorm_kernel(
    const float* __restrict__ x, const float* __restrict__ gamma,
    const float* __restrict__ beta, float* __restrict__ out)
{
    int row = blockIdx.x;
    int tid = threadIdx.x;
    const float* xr = x + (size_t)row * DD;

    float v0 = xr[tid], v1 = xr[tid + 256], v2 = xr[tid + 512];
    float s = v0 + v1 + v2;

    __shared__ float red[8];
    __shared__ float mu_s, rs_s;

    #pragma unroll
    for (int off = 16; off; off >>= 1) s += __shfl_xor_sync(0xffffffffu, s, off);
    if ((tid & 31) == 0) red[tid >> 5] = s;
    __syncthreads();
    if (tid == 0) {
        float t = 0.f;
        #pragma unroll
        for (int i = 0; i < 8; i++) t += red[i];
        mu_s = t * (1.0f / (float)DD);
    }
    __syncthreads();
    float mu = mu_s;
    float d0 = v0 - mu, d1 = v1 - mu, d2 = v2 - mu;
    float q = d0 * d0 + d1 * d1 + d2 * d2;
    #pragma unroll
    for (int off = 16; off; off >>= 1) q += __shfl_xor_sync(0xffffffffu, q, off);
    if ((tid & 31) == 0) red[tid >> 5] = q;
    __syncthreads();
    if (tid == 0) {
        float t = 0.f;
        #pragma unroll
        for (int i = 0; i < 8; i++) t += red[i];
        rs_s = rsqrtf(t * (1.0f / (float)DD) + EPSV);
    }
    __syncthreads();
    float rs = rs_s;
    float* orow = out + (size_t)row * DD;
    orow[tid]       = d0 * rs * gamma[tid]       + beta[tid];
    orow[tid + 256] = d1 * rs * gamma[tid + 256] + beta[tid + 256];
    orow[tid + 512] = d2 * rs * gamma[tid + 512] + beta[tid + 512];
}

// =====================================================================
// fp16 mma.sync GEMM with ldmatrix fragments
//   C[M,N] = alpha*A[M,K]@B + bias + relu + res
//   A: [M,K] row-major fp32 (converted to half in-kernel)
//   Bt: [N,K] row-major HALF (pre-transposed/converted)
//   block 128x128, K chunks of 32, double-buffered smem (1 sync/chunk),
//   8 warps (2x4) of 64x32 warp tiles, m16n8k16 fp16 mma, fp32 accum.
//   SMEM tiles: [128 rows][32 half] = rows of 4 x 16B chunks, XOR-swizzled
//   chunk' = chunk ^ ((row>>1)&3)  -> conflict-free STS.128 and ldmatrix.
// =====================================================================
template<bool BIAS, bool RELU, bool RES, bool QKVS>
__global__ __launch_bounds__(256, 2) void mma_gemm(
    int M, int N, int K, float alpha,
    const float* __restrict__ A, const __half* __restrict__ Bt,
    const float* __restrict__ bias, const float* __restrict__ res,
    float* __restrict__ C)
{
    __shared__ uint32_t As2[2][2048];   // 8KB per stage
    __shared__ uint32_t Bs2[2][2048];

    const int tid  = threadIdx.x;
    const int lane = tid & 31, wid = tid >> 5;
    const int g = lane >> 2, t4 = lane & 3;
    const int wm = wid & 1, wn = wid >> 1;       // warp grid 2 (m) x 4 (n)
    const int brow = blockIdx.y * 128;
    const int bcol = blockIdx.x * 128;

    // ---- staging geometry: thread handles (row = tid>>1, k-half = tid&1) ----
    const int sr  = tid >> 1;
    const int sks = tid & 1;
    const int ssw = (tid >> 2) & 3;              // (row>>1)&3
    const uint32_t aSt0 = 64u * sr + 16u * ((2 * sks + 0) ^ ssw);
    const uint32_t aSt1 = 64u * sr + 16u * ((2 * sks + 1) ^ ssw);
    const float*  Ag = A  + (size_t)(brow + sr) * K + sks * 16;
    const __half* Bg = Bt + (size_t)(bcol + sr) * K + sks * 16;

    // ---- ldmatrix per-lane geometry ----
    const int rA  = ((lane >> 3) & 1) * 8 + (lane & 7);
    const int cA  = lane >> 4;                   // 0/1 -> k chunk parity
    const int swA = (rA >> 1) & 3;
    const int rB  = ((lane >> 4) & 1) * 8 + (lane & 7);
    const int cB  = (lane >> 3) & 1;
    const int swB = (rB >> 1) & 3;

    const uint32_t aBase = smem_u32(As2) + 64u * rA;
    const uint32_t bBase = smem_u32(Bs2) + 64u * rB;

    float acc[4][4][4];
    #pragma unroll
    for (int mt = 0; mt < 4; mt++)
        #pragma unroll
        for (int nt = 0; nt < 4; nt++)
            #pragma unroll
            for (int r = 0; r < 4; r++) acc[mt][nt][r] = 0.f;

    const int nc = K >> 5;
    float4 va[4];
    uint4  vbu[2];

    char* smemA = (char*)As2;
    char* smemB = (char*)Bs2;

    // prologue: load + stage chunk 0
    #pragma unroll
    for (int i = 0; i < 4; i++) va[i] = *(const float4*)(Ag + i * 4);
    vbu[0] = *(const uint4*)(Bg);
    vbu[1] = *(const uint4*)(Bg + 8);
    {
        const float* af = (const float*)va;
        uint4 ua0, ua1;
        ua0.x = pack_h2(af[0], af[1]);  ua0.y = pack_h2(af[2], af[3]);
        ua0.z = pack_h2(af[4], af[5]);  ua0.w = pack_h2(af[6], af[7]);
        ua1.x = pack_h2(af[8], af[9]);  ua1.y = pack_h2(af[10], af[11]);
        ua1.z = pack_h2(af[12], af[13]); ua1.w = pack_h2(af[14], af[15]);
        *(uint4*)(smemA + aSt0) = ua0;
        *(uint4*)(smemA + aSt1) = ua1;
        *(uint4*)(smemB + aSt0) = vbu[0];
        *(uint4*)(smemB + aSt1) = vbu[1];
    }
    __syncthreads();

    for (int ch = 0; ch < nc; ch++) {
        const bool more = (ch + 1 < nc);
        const int s = ch & 1;
        if (more) {
            const int k0 = (ch + 1) << 5;
            #pragma unroll
            for (int i = 0; i < 4; i++) va[i] = *(const float4*)(Ag + k0 + i * 4);
            vbu[0] = *(const uint4*)(Bg + k0);
            vbu[1] = *(const uint4*)(Bg + k0 + 8);
        }

        // ---- MMA over the 32-K chunk from stage s (ldmatrix fragments) ----
        const uint32_t aS = aBase + (uint32_t)s * 8192u;
        const uint32_t bS = bBase + (uint32_t)s * 8192u;
        #pragma unroll
        for (int ks = 0; ks < 2; ks++) {
            uint32_t af[4][4], bf[2][4];
            const uint32_t aCh = 16u * (uint32_t)((2 * ks + cA) ^ swA);
            const uint32_t bCh = 16u * (uint32_t)((2 * ks + cB) ^ swB);
            #pragma unroll
            for (int mt = 0; mt < 4; mt++)
                ldsm4(af[mt], aS + 1024u * (uint32_t)(wm * 4 + mt) + aCh);
            #pragma unroll
            for (int jj = 0; jj < 2; jj++)
                ldsm4(bf[jj], bS + 1024u * (uint32_t)(wn * 2 + jj) + bCh);
            #pragma unroll
            for (int mt = 0; mt < 4; mt++)
                #pragma unroll
                for (int nt = 0; nt < 4; nt++)
                    mma16(acc[mt][nt], af[mt], &bf[nt >> 1][(nt & 1) * 2]);
        }

        if (more) {
            const float* af = (const float*)va;
            uint4 ua0, ua1;
            ua0.x = pack_h2(af[0], af[1]);  ua0.y = pack_h2(af[2], af[3]);
            ua0.z = pack_h2(af[4], af[5]);  ua0.w = pack_h2(af[6], af[7]);
            ua1.x = pack_h2(af[8], af[9]);  ua1.y = pack_h2(af[10], af[11]);
            ua1.z = pack_h2(af[12], af[13]); ua1.w = pack_h2(af[14], af[15]);
            char* An = smemA + (s ^ 1) * 8192;
            char* Bn = smemB + (s ^ 1) * 8192;
            *(uint4*)(An + aSt0) = ua0;
            *(uint4*)(An + aSt1) = ua1;
            *(uint4*)(Bn + aSt0) = vbu[0];
            *(uint4*)(Bn + aSt1) = vbu[1];
            __syncthreads();
        }
    }

    // ---- epilogue (fp32) ----
    const float aeff = QKVS ? ((bcol < DD) ? alpha : 1.0f) : alpha;
    #pragma unroll
    for (int mt = 0; mt < 4; mt++) {
        const int row0 = brow + wm * 64 + mt * 16 + g;
        const int row1 = row0 + 8;
        #pragma unroll
        for (int nt = 0; nt < 4; nt++) {
            const int col = bcol + wn * 32 + nt * 8 + t4 * 2;
            float2 lo, hi;
            lo.x = acc[mt][nt][0] * aeff; lo.y = acc[mt][nt][1] * aeff;
            hi.x = acc[mt][nt][2] * aeff; hi.y = acc[mt][nt][3] * aeff;
            if (BIAS) {
                const float2 bb = *(const float2*)&bias[col];
                lo.x += bb.x; lo.y += bb.y; hi.x += bb.x; hi.y += bb.y;
            }
            if (RELU) {
                lo.x = fmaxf(lo.x, 0.f); lo.y = fmaxf(lo.y, 0.f);
                hi.x = fmaxf(hi.x, 0.f); hi.y = fmaxf(hi.y, 0.f);
            }
            if (RES) {
                const float2 r0 = *(const float2*)&res[(size_t)row0 * N + col];
                const float2 r1 = *(const float2*)&res[(size_t)row1 * N + col];
                lo.x += r0.x; lo.y += r0.y; hi.x += r1.x; hi.y += r1.y;
            }
            *(float2*)&C[(size_t)row0 * N + col] = lo;
            *(float2*)&C[(size_t)row1 * N + col] = hi;
        }
    }
}

// =====================================================================
// BigBird flash attention (fp32)
//   grid (NB=64, H=12, B=2), 256 threads (8 warps), warp w owns rows w+8i.
//   q/k/v live in the fused QKV buffer: row stride QKVD.
// =====================================================================
struct PlanT { int v[(NBB - 2) * 8]; };

__global__ __launch_bounds__(256) void attn_kernel(
    const float* __restrict__ q, const float* __restrict__ k,
    const float* __restrict__ v, const PlanT plan,
    float* __restrict__ ctx)
{
    __shared__ float Qs[64 * 64];   // 16 KB
    __shared__ float Ks[32 * 68];   // padded: conflict-free lane-major reads
    __shared__ float Vs[32 * 64];
    __shared__ float Ps[64 * 33];   // padded P stage

    const int qb = blockIdx.x, h = blockIdx.y, b = blockIdx.z;
    const int tid = threadIdx.x;
    const int w = tid >> 5, lane = tid & 31;

    // load Q tile (pre-scaled by 1/sqrt(HD) in the fused QKV GEMM)
    const size_t qbase = ((size_t)(b * LL + qb * 64)) * QKVD + h * HDD;
    #pragma unroll
    for (int i = 0; i < 4; i++) {
        int f = tid + i * 256;        // 1024 float4s total
        int r = f >> 4, d4 = (f & 15) * 4;
        *(float4*)&Qs[r * 64 + d4] = *(const float4*)&q[qbase + (size_t)r * QKVD + d4];
    }

    float mreg[8], lreg[8], o0[8], o1[8];
    #pragma unroll
    for (int i = 0; i < 8; i++) { mreg[i] = -1e30f; lreg[i] = 0.f; o0[i] = 0.f; o1[i] = 0.f; }

    const int nkb = (qb == 0 || qb == NBB - 1) ? NBB : 8;

    for (int kbi = 0; kbi < nkb; kbi++) {
        int kb = (nkb == NBB) ? kbi : plan.v[(qb - 1) * 8 + kbi];
        for (int half = 0; half < 2; half++) {
            __syncthreads();   // protect Ks/Vs (and first-iter Qs) from prior consumers
            const size_t kbase = ((size_t)(b * LL + kb * 64 + half * 32)) * QKVD + h * HDD;
            #pragma unroll
            for (int i = 0; i < 2; i++) {
                int f = tid + i * 256;    // 512 float4s
                int c = f >> 4, d4 = (f & 15) * 4;
                *(float4*)&Ks[c * 68 + d4] = *(const float4*)&k[kbase + (size_t)c * QKVD + d4];
                *(float4*)&Vs[c * 64 + d4] = *(const float4*)&v[kbase + (size_t)c * QKVD + d4];
            }
            __syncthreads();

            // ---- QK^T + online softmax, one row at a time per warp ----
            #pragma unroll
            for (int i = 0; i < 8; i++) {
                int r = w + i * 8;
                const float4* qr = (const float4*)&Qs[r * 64];
                const float4* kr = (const float4*)&Ks[lane * 68];
                float s = 0.f;
                #pragma unroll
                for (int d4 = 0; d4 < 16; d4++) {
                    float4 a = qr[d4]; float4 bb = kr[d4];
                    s += a.x * bb.x + a.y * bb.y + a.z * bb.z + a.w * bb.w;
                }
                float cm = s;
                #pragma unroll
                for (int off = 16; off; off >>= 1)
                    cm = fmaxf(cm, __shfl_xor_sync(0xffffffffu, cm, off));
                float mn = fmaxf(mreg[i], cm);
                float sc = __expf(mreg[i] - mn);
                float p  = __expf(s - mn);
                float ps = p;
                #pragma unroll
                for (int off = 16; off; off >>= 1)
                    ps += __shfl_xor_sync(0xffffffffu, ps, off);
                lreg[i] = lreg[i] * sc + ps;
                mreg[i] = mn;
                o0[i] *= sc; o1[i] *= sc;
                Ps[r * 33 + lane] = p;
            }
            __syncwarp();

            // ---- P @ V: lane owns output dims (lane, lane+32), 2 rows at a time ----
            #pragma unroll
            for (int i = 0; i < 8; i += 2) {
                int r0 = w + i * 8, r1 = r0 + 8;
                float a0 = o0[i], a1 = o1[i], b0 = o0[i + 1], b1 = o1[i + 1];
                #pragma unroll
                for (int c = 0; c < 32; c++) {
                    float vv0 = Vs[c * 64 + lane];
                    float vv1 = Vs[c * 64 + lane + 32];
                    float p0 = Ps[r0 * 33 + c];
                    float p1 = Ps[r1 * 33 + c];
                    a0 += p0 * vv0; a1 += p0 * vv1;
                    b0 += p1 * vv0; b1 += p1 * vv1;
                }
                o0[i] = a0; o1[i] = a1; o0[i + 1] = b0; o1[i + 1] = b1;
            }
        }
    }

    // write context in [B*L, D] layout (col = h*64 + d) for the Wo GEMM
    const size_t obase = ((size_t)(b * LL + qb * 64)) * DD + h * HDD;
    #pragma unroll
    for (int i = 0; i < 8; i++) {
        int r = w + i * 8;
        float inv = 1.0f / lreg[i];
        ctx[obase + (size_t)r * DD + lane]      = o0[i] * inv;
        ctx[obase + (size_t)r * DD + lane + 32] = o1[i] * inv;
    }
}

// =====================================================================
// host-side numpy MT19937 (legacy RandomState(0)) -> BigBird plan
// =====================================================================
namespace hostmt {
struct MT {
    unsigned int key[624];
    int pos;
};
static void mt_seed(MT& s, unsigned int seed) {
    for (int p = 0; p < 624; p++) {
        s.key[p] = seed;
        seed = 1812433253u * (seed ^ (seed >> 30)) + (unsigned)p + 1u;
    }
    s.pos = 624;
}
static unsigned int mt_next(MT& s) {
    if (s.pos == 624) {
        for (int i = 0; i < 624; i++) {
            unsigned int y = (s.key[i] & 0x80000000u) | (s.key[(i + 1) % 624] & 0x7fffffffu);
            s.key[i] = s.key[(i + 397) % 624] ^ (y >> 1) ^ ((y & 1u) ? 0x9908b0dfu : 0u);
        }
        s.pos = 0;
    }
    unsigned int y = s.key[s.pos++];
    y ^= y >> 11;
    y ^= (y << 7)  & 0x9d2c5680u;
    y ^= (y << 15) & 0xefc60000u;
    y ^= y >> 18;
    return y;
}
static unsigned int mt_interval(MT& s, unsigned int mx) {
    if (mx == 0u) return 0u;
    unsigned int mask = mx;
    mask |= mask >> 1; mask |= mask >> 2; mask |= mask >> 4;
    mask |= mask >> 8; mask |= mask >> 16;
    unsigned int v;
    while ((v = (mt_next(s) & mask)) > mx) { }
    return v;
}
static void make_plan(int* plan) {
    MT st;
    mt_seed(st, 0u);
    for (int i = 1; i <= NBB - 2; i++) {
        int cand[64]; int n = 0;
        for (int j = 0; j < NBB; j++) {
            if (j == 0 || j == NBB - 1 || j == i - 1 || j == i || j == i + 1) continue;
            cand[n++] = j;
        }
        int perm[64];
        for (int j = 0; j < n; j++) perm[j] = j;
        for (int ii = n - 1; ii >= 1; ii--) {
            int j = (int)mt_interval(st, (unsigned)ii);
            int t = perm[ii]; perm[ii] = perm[j]; perm[j] = t;
        }
        int* row = plan + (i - 1) * 8;
        row[0] = 0; row[1] = NBB - 1; row[2] = i - 1; row[3] = i; row[4] = i + 1;
        for (int t = 0; t < 3; t++) row[5 + t] = cand[perm[t]];
    }
}
} // namespace hostmt

// =====================================================================
// launch
// =====================================================================
extern "C" void kernel_launch(void* const* d_in, const int* in_sizes, int n_in,
                              void* d_out, int out_size)
{
    (void)in_sizes; (void)n_in; (void)out_size;
    const float* x    = (const float*)d_in[0];
    const float* ln1s = (const float*)d_in[1];
    const float* ln1b = (const float*)d_in[2];
    const float* Wq   = (const float*)d_in[3];   // [D, H*HD] flat
    const float* Wk   = (const float*)d_in[4];
    const float* Wv   = (const float*)d_in[5];
    const float* Wo   = (const float*)d_in[6];   // [H*HD, D] flat
    const float* ln2s = (const float*)d_in[7];
    const float* ln2b = (const float*)d_in[8];
    const float* W1   = (const float*)d_in[9];   // [D, MLP]
    const float* b1   = (const float*)d_in[10];
    const float* W2   = (const float*)d_in[11];  // [MLP, D]
    const float* b2   = (const float*)d_in[12];
    float* out = (float*)d_out;

    void *ph, *pqkv, *pctx, *px1, *py, *pz;
    void *pwqkvt, *pwot, *pw1t, *pw2t;
    cudaGetSymbolAddress(&ph,    g_h);
    cudaGetSymbolAddress(&pqkv,  g_qkv);
    cudaGetSymbolAddress(&pctx,  g_ctx);
    cudaGetSymbolAddress(&px1,   g_x1);
    cudaGetSymbolAddress(&py,    g_y);
    cudaGetSymbolAddress(&pz,    g_z);
    cudaGetSymbolAddress(&pwqkvt, g_wqkvt);
    cudaGetSymbolAddress(&pwot,  g_wot);
    cudaGetSymbolAddress(&pw1t,  g_w1t);
    cudaGetSymbolAddress(&pw2t,  g_w2t);

    float*  fh    = (float*)ph;
    float*  fqkv  = (float*)pqkv;
    float*  fctx  = (float*)pctx;
    float*  fx1   = (float*)px1;
    float*  fy    = (float*)py;
    float*  fz    = (float*)pz;
    __half* wqkvt = (__half*)pwqkvt;
    __half* wot   = (__half*)pwot;
    __half* w1t   = (__half*)pw1t;
    __half* w2t   = (__half*)pw2t;

    // host-computed BigBird plan (numpy MT19937 replica) as kernel param
    PlanT plan;
    hostmt::make_plan(plan.v);

    dim3 tb(32, 8);

    // #1-#3 (ncu captures my 4th launch -> make it the QKV GEMM)
    transpose3_h_kernel<<<dim3(DD / 32, DD / 32, 3), tb>>>(Wq, Wk, Wv, wqkvt);
    transpose_h_kernel<<<dim3(DD / 32, DD / 32), tb>>>(Wo, wot, DD, DD);
    layernorm_kernel<<<ROWS, 256>>>(x, ln1s, ln1b, fh);

    // #4: fused QKV GEMM, N=2304, q-segment scaled by 0.125
    dim3 gqkv(QKVD / 128, ROWS / 128);
    mma_gemm<false, false, false, true><<<gqkv, 256>>>(ROWS, QKVD, DD, 0.125f, fh, wqkvt, nullptr, nullptr, fqkv);

    // remaining transposes (needed before the MLP GEMMs)
    transpose_h_kernel<<<dim3(MLPD / 32, DD / 32), tb>>>(W1, w1t, DD, MLPD);
    transpose_h_kernel<<<dim3(DD / 32, MLPD / 32), tb>>>(W2, w2t, MLPD, DD);

    // BigBird attention -> ctx [B*L, D]
    attn_kernel<<<dim3(NBB, HH, BB), 256>>>(fqkv, fqkv + DD, fqkv + 2 * DD, plan, fctx);

    // x1 = ctx @ Wo + x
    dim3 gdd(DD / 128, ROWS / 128);
    mma_gemm<false, false, true, false><<<gdd, 256>>>(ROWS, DD, DD, 1.0f, fctx, wot, nullptr, x, fx1);

    // y = LN2(x1)
    layernorm_kernel<<<ROWS, 256>>>(fx1, ln2s, ln2b, fy);

    // z = relu(y @ W1 + b1)
    dim3 gm1(MLPD / 128, ROWS / 128);
    mma_gemm<true, true, false, false><<<gm1, 256>>>(ROWS, MLPD, DD, 1.0f, fy, w1t, b1, nullptr, fz);

    // out = z @ W2 + b2 + x1
    mma_gemm<true, false, true, false><<<gdd, 256>>>(ROWS, DD, MLPD, 1.0f, fz, w2t, b2, fx1, out);
}

// round 9
// speedup vs baseline: 1.2123x; 1.2123x over previous
#include <cuda_runtime.h>
#include <cuda_fp16.h>
#include <cstdint>

// ---------------- problem dims ----------------
#define BB   2
#define LL   4096
#define DD   768
#define HH   12
#define HDD  64
#define NBB  64
#define MLPD 3072
#define ROWS (BB*LL)      // 8192
#define QKVD (3*DD)       // 2304
#define EPSV 1e-6f

// ---------------- scratch (device globals; no allocation allowed) ------------
__device__ __half g_h  [ROWS*DD];     // LN1 out (half)
__device__ float  g_qkv[ROWS*QKVD];   // fused qkv (fp32 for exact attention)
__device__ __half g_ctx[ROWS*DD];     // attention out (half)
__device__ float  g_x1 [ROWS*DD];     // residual 1 (fp32)
__device__ __half g_y  [ROWS*DD];     // LN2 out (half)
__device__ __half g_z  [ROWS*MLPD];   // relu out (half)
// transposed (K-major) weights, pre-converted to half
__device__ __half g_wqkvt[QKVD*DD];   // rows: [Wq^T ; Wk^T ; Wv^T]
__device__ __half g_wot[DD*DD];
__device__ __half g_w1t[MLPD*DD];
__device__ __half g_w2t[DD*MLPD];

// =====================================================================
// helpers
// =====================================================================
__device__ __forceinline__ uint32_t smem_u32(const void* p) {
    uint32_t a;
    asm("{ .reg .u64 t; cvta.to.shared.u64 t, %1; cvt.u32.u64 %0, t; }" : "=r"(a) : "l"(p));
    return a;
}

__device__ __forceinline__ void mma16(float* d, const uint32_t* a, const uint32_t* b) {
    asm volatile(
        "mma.sync.aligned.m16n8k16.row.col.f32.f16.f16.f32 "
        "{%0,%1,%2,%3}, {%4,%5,%6,%7}, {%8,%9}, {%0,%1,%2,%3};"
        : "+f"(d[0]), "+f"(d[1]), "+f"(d[2]), "+f"(d[3])
        : "r"(a[0]), "r"(a[1]), "r"(a[2]), "r"(a[3]), "r"(b[0]), "r"(b[1]));
}

__device__ __forceinline__ void ldsm4(uint32_t* r, uint32_t addr) {
    asm volatile("ldmatrix.sync.aligned.m8n8.x4.shared.b16 {%0,%1,%2,%3}, [%4];"
        : "=r"(r[0]), "=r"(r[1]), "=r"(r[2]), "=r"(r[3]) : "r"(addr));
}

__device__ __forceinline__ void cp16(uint32_t dst, const void* src) {
    asm volatile("cp.async.cg.shared.global [%0], [%1], 16;" :: "r"(dst), "l"(src) : "memory");
}
#define CP_COMMIT() asm volatile("cp.async.commit_group;" ::: "memory")
#define CP_WAIT1()  asm volatile("cp.async.wait_group 1;" ::: "memory")

// ---- packed fp32x2 (Blackwell base ISA, sm_100+) ----
__device__ __forceinline__ uint64_t pk2(float lo, float hi) {
    uint64_t r; asm("mov.b64 %0, {%1, %2};" : "=l"(r) : "f"(lo), "f"(hi)); return r;
}
__device__ __forceinline__ void upk2(uint64_t v, float& lo, float& hi) {
    asm("mov.b64 {%0, %1}, %2;" : "=f"(lo), "=f"(hi) : "l"(v));
}
__device__ __forceinline__ uint64_t fma2(uint64_t a, uint64_t b, uint64_t c) {
    uint64_t d; asm("fma.rn.f32x2 %0, %1, %2, %3;" : "=l"(d) : "l"(a), "l"(b), "l"(c)); return d;
}
__device__ __forceinline__ uint64_t mul2(uint64_t a, uint64_t b) {
    uint64_t d; asm("mul.rn.f32x2 %0, %1, %2;" : "=l"(d) : "l"(a), "l"(b)); return d;
}

// =====================================================================
// transpose (fp32 in -> half out): out[C,R] = half(in[R,C]^T)
// =====================================================================
__global__ __launch_bounds__(256) void transpose_h_kernel(
    const float* __restrict__ in, __half* __restrict__ out, int R, int C)
{
    __shared__ float t[32][33];
    int c0 = blockIdx.x * 32, r0 = blockIdx.y * 32;
    int x = threadIdx.x, y = threadIdx.y;
    #pragma unroll
    for (int i = 0; i < 32; i += 8)
        t[y + i][x] = in[(size_t)(r0 + y + i) * C + c0 + x];
    __syncthreads();
    #pragma unroll
    for (int i = 0; i < 32; i += 8)
        out[(size_t)(c0 + y + i) * R + r0 + x] = __float2half(t[x][y + i]);
}

// batched 3-matrix transpose (Wq, Wk, Wv -> slices of g_wqkvt), each DD x DD
__global__ __launch_bounds__(256) void transpose3_h_kernel(
    const float* __restrict__ s0, const float* __restrict__ s1,
    const float* __restrict__ s2, __half* __restrict__ out)
{
    __shared__ float t[32][33];
    const float* in = (blockIdx.z == 0) ? s0 : (blockIdx.z == 1) ? s1 : s2;
    __half* o = out + (size_t)blockIdx.z * DD * DD;
    int c0 = blockIdx.x * 32, r0 = blockIdx.y * 32;
    int x = threadIdx.x, y = threadIdx.y;
    #pragma unroll
    for (int i = 0; i < 32; i += 8)
        t[y + i][x] = in[(size_t)(r0 + y + i) * DD + c0 + x];
    __syncthreads();
    #pragma unroll
    for (int i = 0; i < 32; i += 8)
        o[(size_t)(c0 + y + i) * DD + r0 + x] = __float2half(t[x][y + i]);
}

// =====================================================================
// LayerNorm (fp32 in -> half out): one block (256 thr) per row
// =====================================================================
__global__ __launch_bounds__(256) void layernorm_kernel(
    const float* __restrict__ x, const float* __restrict__ gamma,
    const float* __restrict__ beta, __half* __restrict__ out)
{
    int row = blockIdx.x;
    int tid = threadIdx.x;
    const float* xr = x + (size_t)row * DD;

    float v0 = xr[tid], v1 = xr[tid + 256], v2 = xr[tid + 512];
    float s = v0 + v1 + v2;

    __shared__ float red[8];
    __shared__ float mu_s, rs_s;

    #pragma unroll
    for (int off = 16; off; off >>= 1) s += __shfl_xor_sync(0xffffffffu, s, off);
    if ((tid & 31) == 0) red[tid >> 5] = s;
    __syncthreads();
    if (tid == 0) {
        float t = 0.f;
        #pragma unroll
        for (int i = 0; i < 8; i++) t += red[i];
        mu_s = t * (1.0f / (float)DD);
    }
    __syncthreads();
    float mu = mu_s;
    float d0 = v0 - mu, d1 = v1 - mu, d2 = v2 - mu;
    float q = d0 * d0 + d1 * d1 + d2 * d2;
    #pragma unroll
    for (int off = 16; off; off >>= 1) q += __shfl_xor_sync(0xffffffffu, q, off);
    if ((tid & 31) == 0) red[tid >> 5] = q;
    __syncthreads();
    if (tid == 0) {
        float t = 0.f;
        #pragma unroll
        for (int i = 0; i < 8; i++) t += red[i];
        rs_s = rsqrtf(t * (1.0f / (float)DD) + EPSV);
    }
    __syncthreads();
    float rs = rs_s;
    __half* orow = out + (size_t)row * DD;
    orow[tid]       = __float2half(d0 * rs * gamma[tid]       + beta[tid]);
    orow[tid + 256] = __float2half(d1 * rs * gamma[tid + 256] + beta[tid + 256]);
    orow[tid + 512] = __float2half(d2 * rs * gamma[tid + 512] + beta[tid + 512]);
}

// =====================================================================
// fp16 mma GEMM, cp.async 3-stage pipeline, ldmatrix fragments
//   A: [M,K] HALF row-major ; Bt: [N,K] HALF row-major
//   C: fp32 (or half when OUTH) = alpha*A@B + bias + relu + res
//   block 128x128, K chunks of 32, 8 warps (2x4) of 64x32 warp tiles.
//   SMEM: [128 rows][32 half], 16B-chunk swizzle  c' = c ^ ((row>>1)&3).
// =====================================================================
template<bool BIAS, bool RELU, bool RES, bool QKVS, bool OUTH>
__global__ __launch_bounds__(256, 2) void mma_gemm(
    int M, int N, int K, float alpha,
    const __half* __restrict__ A, const __half* __restrict__ Bt,
    const float* __restrict__ bias, const float* __restrict__ res,
    void* __restrict__ Cv)
{
    __shared__ uint32_t As3[3][2048];   // 8KB per stage
    __shared__ uint32_t Bs3[3][2048];

    const int tid  = threadIdx.x;
    const int lane = tid & 31, wid = tid >> 5;
    const int g = lane >> 2, t4 = lane & 3;
    const int wm = wid & 1, wn = wid >> 1;       // warp grid 2 (m) x 4 (n)
    const int brow = blockIdx.y * 128;
    const int bcol = blockIdx.x * 128;

    // ---- cp.async staging geometry: thread -> (row = tid>>1, 16-half group = tid&1)
    const int sr  = tid >> 1;
    const int sks = tid & 1;
    const int ssw = (sr >> 1) & 3;
    const uint32_t d0 = 64u * sr + 16u * (uint32_t)((2 * sks + 0) ^ ssw);
    const uint32_t d1 = 64u * sr + 16u * (uint32_t)((2 * sks + 1) ^ ssw);
    const uint32_t aSm = smem_u32(As3);
    const uint32_t bSm = smem_u32(Bs3);
    const __half* Ag = A  + (size_t)(brow + sr) * K + sks * 16;
    const __half* Bg = Bt + (size_t)(bcol + sr) * K + sks * 16;

    // ---- ldmatrix per-lane geometry ----
    const int rA  = ((lane >> 3) & 1) * 8 + (lane & 7);
    const int cA  = lane >> 4;
    const int swA = (rA >> 1) & 3;
    const int rB  = ((lane >> 4) & 1) * 8 + (lane & 7);
    const int cB  = (lane >> 3) & 1;
    const int swB = (rB >> 1) & 3;
    const uint32_t aBase = aSm + 64u * rA;
    const uint32_t bBase = bSm + 64u * rB;

    float acc[4][4][4];
    #pragma unroll
    for (int mt = 0; mt < 4; mt++)
        #pragma unroll
        for (int nt = 0; nt < 4; nt++)
            #pragma unroll
            for (int r = 0; r < 4; r++) acc[mt][nt][r] = 0.f;

    const int nc = K >> 5;

    // prologue: stage chunks 0 and 1
    #pragma unroll
    for (int p = 0; p < 2; p++) {
        const uint32_t so = (uint32_t)p * 8192u;
        cp16(aSm + so + d0, Ag + p * 32);
        cp16(aSm + so + d1, Ag + p * 32 + 8);
        cp16(bSm + so + d0, Bg + p * 32);
        cp16(bSm + so + d1, Bg + p * 32 + 8);
        CP_COMMIT();
    }

    int sbuf = 0;
    for (int ch = 0; ch < nc; ch++) {
        CP_WAIT1();
        __syncthreads();

        // ---- MMA over chunk ch from stage sbuf ----
        const uint32_t aS = aBase + (uint32_t)sbuf * 8192u;
        const uint32_t bS = bBase + (uint32_t)sbuf * 8192u;
        #pragma unroll
        for (int ks = 0; ks < 2; ks++) {
            uint32_t af[4][4], bf[2][4];
            const uint32_t aCh = 16u * (uint32_t)((2 * ks + cA) ^ swA);
            const uint32_t bCh = 16u * (uint32_t)((2 * ks + cB) ^ swB);
            #pragma unroll
            for (int mt = 0; mt < 4; mt++)
                ldsm4(af[mt], aS + 1024u * (uint32_t)(wm * 4 + mt) + aCh);
            #pragma unroll
            for (int jj = 0; jj < 2; jj++)
                ldsm4(bf[jj], bS + 1024u * (uint32_t)(wn * 2 + jj) + bCh);
            #pragma unroll
            for (int mt = 0; mt < 4; mt++)
                #pragma unroll
                for (int nt = 0; nt < 4; nt++)
                    mma16(acc[mt][nt], af[mt], &bf[nt >> 1][(nt & 1) * 2]);
        }

        // issue chunk ch+2 into the stage being vacated next
        if (ch + 2 < nc) {
            const int ns = (ch + 2) % 3;
            const uint32_t so = (uint32_t)ns * 8192u;
            const int k0 = (ch + 2) * 32;
            cp16(aSm + so + d0, Ag + k0);
            cp16(aSm + so + d1, Ag + k0 + 8);
            cp16(bSm + so + d0, Bg + k0);
            cp16(bSm + so + d1, Bg + k0 + 8);
        }
        CP_COMMIT();
        sbuf = (sbuf + 1 == 3) ? 0 : sbuf + 1;
    }

    // ---- epilogue ----
    const float aeff = QKVS ? ((bcol < DD) ? alpha : 1.0f) : alpha;
    float*  Cf = (float*)Cv;
    __half* Ch = (__half*)Cv;
    #pragma unroll
    for (int mt = 0; mt < 4; mt++) {
        const int row0 = brow + wm * 64 + mt * 16 + g;
        const int row1 = row0 + 8;
        #pragma unroll
        for (int nt = 0; nt < 4; nt++) {
            const int col = bcol + wn * 32 + nt * 8 + t4 * 2;
            float2 lo, hi;
            lo.x = acc[mt][nt][0] * aeff; lo.y = acc[mt][nt][1] * aeff;
            hi.x = acc[mt][nt][2] * aeff; hi.y = acc[mt][nt][3] * aeff;
            if (BIAS) {
                const float2 bb = *(const float2*)&bias[col];
                lo.x += bb.x; lo.y += bb.y; hi.x += bb.x; hi.y += bb.y;
            }
            if (RELU) {
                lo.x = fmaxf(lo.x, 0.f); lo.y = fmaxf(lo.y, 0.f);
                hi.x = fmaxf(hi.x, 0.f); hi.y = fmaxf(hi.y, 0.f);
            }
            if (RES) {
                const float2 r0 = *(const float2*)&res[(size_t)row0 * N + col];
                const float2 r1 = *(const float2*)&res[(size_t)row1 * N + col];
                lo.x += r0.x; lo.y += r0.y; hi.x += r1.x; hi.y += r1.y;
            }
            if (OUTH) {
                __half2 hl = __floats2half2_rn(lo.x, lo.y);
                __half2 hh = __floats2half2_rn(hi.x, hi.y);
                *(__half2*)&Ch[(size_t)row0 * N + col] = hl;
                *(__half2*)&Ch[(size_t)row1 * N + col] = hh;
            } else {
                *(float2*)&Cf[(size_t)row0 * N + col] = lo;
                *(float2*)&Cf[(size_t)row1 * N + col] = hi;
            }
        }
    }
}

// =====================================================================
// BigBird flash attention (exact fp32 math, packed f32x2 FMA)
//   grid (NB=64, H=12, B=2), 256 threads (8 warps), warp w owns rows w+8i.
//   Register-blocked: K and V chunks held in regs, reused across 8 rows.
//   Writes ctx as HALF (feeds Wo GEMM).
// =====================================================================
struct PlanT { int v[(NBB - 2) * 8]; };

__global__ __launch_bounds__(256) void attn_kernel(
    const float* __restrict__ q, const float* __restrict__ k,
    const float* __restrict__ v, const PlanT plan,
    __half* __restrict__ ctx)
{
    __shared__ float Qs[64 * 64];   // 16 KB
    __shared__ float Ks[32 * 68];   // padded rows (17 float4) -> conflict-free
    __shared__ float Vs[32 * 64];
    __shared__ float Ps[64 * 33];

    const int qb = blockIdx.x, h = blockIdx.y, b = blockIdx.z;
    const int tid = threadIdx.x;
    const int w = tid >> 5, lane = tid & 31;

    // load Q tile (pre-scaled by 1/sqrt(HD) in the fused QKV GEMM)
    const size_t qbase = ((size_t)(b * LL + qb * 64)) * QKVD + h * HDD;
    #pragma unroll
    for (int i = 0; i < 4; i++) {
        int f = tid + i * 256;
        int r = f >> 4, d4 = (f & 15) * 4;
        *(float4*)&Qs[r * 64 + d4] = *(const float4*)&q[qbase + (size_t)r * QKVD + d4];
    }

    float mreg[8], lreg[8];
    uint64_t od[8];                       // packed (o[lane], o[lane+32]) per row
    const uint64_t z2 = pk2(0.f, 0.f);
    #pragma unroll
    for (int i = 0; i < 8; i++) { mreg[i] = -1e30f; lreg[i] = 0.f; od[i] = z2; }

    const int nkb = (qb == 0 || qb == NBB - 1) ? NBB : 8;

    for (int kbi = 0; kbi < nkb; kbi++) {
        int kb = (nkb == NBB) ? kbi : plan.v[(qb - 1) * 8 + kbi];
        for (int half = 0; half < 2; half++) {
            __syncthreads();   // protect Ks/Vs (and first-iter Qs) from prior readers
            const size_t kbase = ((size_t)(b * LL + kb * 64 + half * 32)) * QKVD + h * HDD;
            #pragma unroll
            for (int i = 0; i < 2; i++) {
                int f = tid + i * 256;
                int c = f >> 4, d4 = (f & 15) * 4;
                *(float4*)&Ks[c * 68 + d4] = *(const float4*)&k[kbase + (size_t)c * QKVD + d4];
                *(float4*)&Vs[c * 64 + d4] = *(const float4*)&v[kbase + (size_t)c * QKVD + d4];
            }
            __syncthreads();

            // ---- QK^T: lane = key, K chunk in regs reused across 8 rows ----
            uint64_t ps[8];
            #pragma unroll
            for (int i = 0; i < 8; i++) ps[i] = z2;
            #pragma unroll
            for (int dc = 0; dc < 4; dc++) {
                const float4* kr = (const float4*)&Ks[lane * 68 + dc * 16];
                float4 k0 = kr[0], k1 = kr[1], k2 = kr[2], k3 = kr[3];
                uint64_t kp0 = pk2(k0.x, k0.y), kp1 = pk2(k0.z, k0.w);
                uint64_t kp2 = pk2(k1.x, k1.y), kp3 = pk2(k1.z, k1.w);
                uint64_t kp4 = pk2(k2.x, k2.y), kp5 = pk2(k2.z, k2.w);
                uint64_t kp6 = pk2(k3.x, k3.y), kp7 = pk2(k3.z, k3.w);
                #pragma unroll
                for (int i = 0; i < 8; i++) {
                    const int r = w + i * 8;
                    const float4* qr = (const float4*)&Qs[r * 64 + dc * 16];
                    float4 q0 = qr[0], q1 = qr[1], q2 = qr[2], q3 = qr[3];
                    ps[i] = fma2(pk2(q0.x, q0.y), kp0, ps[i]);
                    ps[i] = fma2(pk2(q0.z, q0.w), kp1, ps[i]);
                    ps[i] = fma2(pk2(q1.x, q1.y), kp2, ps[i]);
                    ps[i] = fma2(pk2(q1.z, q1.w), kp3, ps[i]);
                    ps[i] = fma2(pk2(q2.x, q2.y), kp4, ps[i]);
                    ps[i] = fma2(pk2(q2.z, q2.w), kp5, ps[i]);
                    ps[i] = fma2(pk2(q3.x, q3.y), kp6, ps[i]);
                    ps[i] = fma2(pk2(q3.z, q3.w), kp7, ps[i]);
                }
            }

            // ---- online softmax per row ----
            #pragma unroll
            for (int i = 0; i < 8; i++) {
                const int r = w + i * 8;
                float slo, shi;
                upk2(ps[i], slo, shi);
                float s = slo + shi;
                float cm = s;
                #pragma unroll
                for (int off = 16; off; off >>= 1)
                    cm = fmaxf(cm, __shfl_xor_sync(0xffffffffu, cm, off));
                float mn = fmaxf(mreg[i], cm);
                float sc = __expf(mreg[i] - mn);
                float p  = __expf(s - mn);
                float pssum = p;
                #pragma unroll
                for (int off = 16; off; off >>= 1)
                    pssum += __shfl_xor_sync(0xffffffffu, pssum, off);
                lreg[i] = lreg[i] * sc + pssum;
                mreg[i] = mn;
                od[i] = mul2(od[i], pk2(sc, sc));
                Ps[r * 33 + lane] = p;
            }
            __syncwarp();

            // ---- P @ V: lane owns dims (lane, lane+32); V chunk in regs ----
            #pragma unroll
            for (int cg = 0; cg < 4; cg++) {
                uint64_t vp[8];
                #pragma unroll
                for (int j = 0; j < 8; j++) {
                    const int c = cg * 8 + j;
                    vp[j] = pk2(Vs[c * 64 + lane], Vs[c * 64 + lane + 32]);
                }
                #pragma unroll
                for (int i = 0; i < 8; i++) {
                    const int r = w + i * 8;
                    const float* pr = &Ps[r * 33 + cg * 8];
                    #pragma unroll
                    for (int j = 0; j < 8; j++) {
                        float p = pr[j];
                        od[i] = fma2(pk2(p, p), vp[j], od[i]);
                    }
                }
            }
        }
    }

    // write context as HALF in [B*L, D] layout (col = h*64 + d)
    const size_t obase = ((size_t)(b * LL + qb * 64)) * DD + h * HDD;
    #pragma unroll
    for (int i = 0; i < 8; i++) {
        const int r = w + i * 8;
        float inv = 1.0f / lreg[i];
        float o0, o1;
        upk2(od[i], o0, o1);
        ctx[obase + (size_t)r * DD + lane]      = __float2half(o0 * inv);
        ctx[obase + (size_t)r * DD + lane + 32] = __float2half(o1 * inv);
    }
}

// =====================================================================
// host-side numpy MT19937 (legacy RandomState(0)) -> BigBird plan
// =====================================================================
namespace hostmt {
struct MT {
    unsigned int key[624];
    int pos;
};
static void mt_seed(MT& s, unsigned int seed) {
    for (int p = 0; p < 624; p++) {
        s.key[p] = seed;
        seed = 1812433253u * (seed ^ (seed >> 30)) + (unsigned)p + 1u;
    }
    s.pos = 624;
}
static unsigned int mt_next(MT& s) {
    if (s.pos == 624) {
        for (int i = 0; i < 624; i++) {
            unsigned int y = (s.key[i] & 0x80000000u) | (s.key[(i + 1) % 624] & 0x7fffffffu);
            s.key[i] = s.key[(i + 397) % 624] ^ (y >> 1) ^ ((y & 1u) ? 0x9908b0dfu : 0u);
        }
        s.pos = 0;
    }
    unsigned int y = s.key[s.pos++];
    y ^= y >> 11;
    y ^= (y << 7)  & 0x9d2c5680u;
    y ^= (y << 15) & 0xefc60000u;
    y ^= y >> 18;
    return y;
}
static unsigned int mt_interval(MT& s, unsigned int mx) {
    if (mx == 0u) return 0u;
    unsigned int mask = mx;
    mask |= mask >> 1; mask |= mask >> 2; mask |= mask >> 4;
    mask |= mask >> 8; mask |= mask >> 16;
    unsigned int v;
    while ((v = (mt_next(s) & mask)) > mx) { }
    return v;
}
static void make_plan(int* plan) {
    MT st;
    mt_seed(st, 0u);
    for (int i = 1; i <= NBB - 2; i++) {
        int cand[64]; int n = 0;
        for (int j = 0; j < NBB; j++) {
            if (j == 0 || j == NBB - 1 || j == i - 1 || j == i || j == i + 1) continue;
            cand[n++] = j;
        }
        int perm[64];
        for (int j = 0; j < n; j++) perm[j] = j;
        for (int ii = n - 1; ii >= 1; ii--) {
            int j = (int)mt_interval(st, (unsigned)ii);
            int t = perm[ii]; perm[ii] = perm[j]; perm[j] = t;
        }
        int* row = plan + (i - 1) * 8;
        row[0] = 0; row[1] = NBB - 1; row[2] = i - 1; row[3] = i; row[4] = i + 1;
        for (int t = 0; t < 3; t++) row[5 + t] = cand[perm[t]];
    }
}
} // namespace hostmt

// =====================================================================
// launch
// =====================================================================
extern "C" void kernel_launch(void* const* d_in, const int* in_sizes, int n_in,
                              void* d_out, int out_size)
{
    (void)in_sizes; (void)n_in; (void)out_size;
    const float* x    = (const float*)d_in[0];
    const float* ln1s = (const float*)d_in[1];
    const float* ln1b = (const float*)d_in[2];
    const float* Wq   = (const float*)d_in[3];   // [D, H*HD] flat
    const float* Wk   = (const float*)d_in[4];
    const float* Wv   = (const float*)d_in[5];
    const float* Wo   = (const float*)d_in[6];   // [H*HD, D] flat
    const float* ln2s = (const float*)d_in[7];
    const float* ln2b = (const float*)d_in[8];
    const float* W1   = (const float*)d_in[9];   // [D, MLP]
    const float* b1   = (const float*)d_in[10];
    const float* W2   = (const float*)d_in[11];  // [MLP, D]
    const float* b2   = (const float*)d_in[12];
    float* out = (float*)d_out;

    void *ph, *pqkv, *pctx, *px1, *py, *pz;
    void *pwqkvt, *pwot, *pw1t, *pw2t;
    cudaGetSymbolAddress(&ph,    g_h);
    cudaGetSymbolAddress(&pqkv,  g_qkv);
    cudaGetSymbolAddress(&pctx,  g_ctx);
    cudaGetSymbolAddress(&px1,   g_x1);
    cudaGetSymbolAddress(&py,    g_y);
    cudaGetSymbolAddress(&pz,    g_z);
    cudaGetSymbolAddress(&pwqkvt, g_wqkvt);
    cudaGetSymbolAddress(&pwot,  g_wot);
    cudaGetSymbolAddress(&pw1t,  g_w1t);
    cudaGetSymbolAddress(&pw2t,  g_w2t);

    __half* fh    = (__half*)ph;
    float*  fqkv  = (float*)pqkv;
    __half* fctx  = (__half*)pctx;
    float*  fx1   = (float*)px1;
    __half* fy    = (__half*)py;
    __half* fz    = (__half*)pz;
    __half* wqkvt = (__half*)pwqkvt;
    __half* wot   = (__half*)pwot;
    __half* w1t   = (__half*)pw1t;
    __half* w2t   = (__half*)pw2t;

    // host-computed BigBird plan (numpy MT19937 replica) as kernel param
    PlanT plan;
    hostmt::make_plan(plan.v);

    dim3 tb(32, 8);

    // #1-#3 (ncu captures my 4th launch -> make it the attention kernel)
    transpose3_h_kernel<<<dim3(DD / 32, DD / 32, 3), tb>>>(Wq, Wk, Wv, wqkvt);
    layernorm_kernel<<<ROWS, 256>>>(x, ln1s, ln1b, fh);
    dim3 gqkv(QKVD / 128, ROWS / 128);
    mma_gemm<false, false, false, true, false><<<gqkv, 256>>>(ROWS, QKVD, DD, 0.125f, fh, wqkvt, nullptr, nullptr, fqkv);

    // #4: BigBird attention -> ctx (half)  [PROFILED]
    attn_kernel<<<dim3(NBB, HH, BB), 256>>>(fqkv, fqkv + DD, fqkv + 2 * DD, plan, fctx);

    // remaining weight transposes
    transpose_h_kernel<<<dim3(DD / 32, DD / 32), tb>>>(Wo, wot, DD, DD);
    transpose_h_kernel<<<dim3(MLPD / 32, DD / 32), tb>>>(W1, w1t, DD, MLPD);
    transpose_h_kernel<<<dim3(DD / 32, MLPD / 32), tb>>>(W2, w2t, MLPD, DD);

    // x1 = ctx @ Wo + x
    dim3 gdd(DD / 128, ROWS / 128);
    mma_gemm<false, false, true, false, false><<<gdd, 256>>>(ROWS, DD, DD, 1.0f, fctx, wot, nullptr, x, fx1);

    // y = LN2(x1)  (half out)
    layernorm_kernel<<<ROWS, 256>>>(fx1, ln2s, ln2b, fy);

    // z = relu(y @ W1 + b1)  (half out)
    dim3 gm1(MLPD / 128, ROWS / 128);
    mma_gemm<true, true, false, false, true><<<gm1, 256>>>(ROWS, MLPD, DD, 1.0f, fy, w1t, b1, nullptr, fz);

    // out = z @ W2 + b2 + x1
    mma_gemm<true, false, true, false, false><<<gdd, 256>>>(ROWS, DD, MLPD, 1.0f, fz, w2t, b2, fx1, out);
}

// round 10
// speedup vs baseline: 1.3679x; 1.1284x over previous
#include <cuda_runtime.h>
#include <cuda_fp16.h>
#include <cstdint>

// ---------------- problem dims ----------------
#define BB   2
#define LL   4096
#define DD   768
#define HH   12
#define HDD  64
#define NBB  64
#define MLPD 3072
#define ROWS (BB*LL)      // 8192
#define QKVD (3*DD)       // 2304
#define EPSV 1e-6f

// ---------------- scratch (device globals; no allocation allowed) ------------
__device__ __half g_h  [ROWS*DD];     // LN1 out (half)
__device__ float  g_qkv[ROWS*QKVD];   // fused qkv (fp32 for exact attention)
__device__ __half g_ctx[ROWS*DD];     // attention out (half)
__device__ float  g_x1 [ROWS*DD];     // residual 1 (fp32)
__device__ __half g_y  [ROWS*DD];     // LN2 out (half)
__device__ __half g_z  [ROWS*MLPD];   // relu out (half)
// transposed (K-major) weights, pre-converted to half
__device__ __half g_wqkvt[QKVD*DD];   // rows: [Wq^T ; Wk^T ; Wv^T]
__device__ __half g_wot[DD*DD];
__device__ __half g_w1t[MLPD*DD];
__device__ __half g_w2t[DD*MLPD];

// =====================================================================
// helpers
// =====================================================================
__device__ __forceinline__ uint32_t smem_u32(const void* p) {
    uint32_t a;
    asm("{ .reg .u64 t; cvta.to.shared.u64 t, %1; cvt.u32.u64 %0, t; }" : "=r"(a) : "l"(p));
    return a;
}

__device__ __forceinline__ void mma16(float* d, const uint32_t* a, const uint32_t* b) {
    asm volatile(
        "mma.sync.aligned.m16n8k16.row.col.f32.f16.f16.f32 "
        "{%0,%1,%2,%3}, {%4,%5,%6,%7}, {%8,%9}, {%0,%1,%2,%3};"
        : "+f"(d[0]), "+f"(d[1]), "+f"(d[2]), "+f"(d[3])
        : "r"(a[0]), "r"(a[1]), "r"(a[2]), "r"(a[3]), "r"(b[0]), "r"(b[1]));
}

__device__ __forceinline__ void ldsm4(uint32_t* r, uint32_t addr) {
    asm volatile("ldmatrix.sync.aligned.m8n8.x4.shared.b16 {%0,%1,%2,%3}, [%4];"
        : "=r"(r[0]), "=r"(r[1]), "=r"(r[2]), "=r"(r[3]) : "r"(addr));
}

__device__ __forceinline__ void cp16(uint32_t dst, const void* src) {
    asm volatile("cp.async.cg.shared.global [%0], [%1], 16;" :: "r"(dst), "l"(src) : "memory");
}
#define CP_COMMIT() asm volatile("cp.async.commit_group;" ::: "memory")
#define CP_WAIT1()  asm volatile("cp.async.wait_group 1;" ::: "memory")

// ---- packed fp32x2 (Blackwell base ISA, sm_100+) ----
__device__ __forceinline__ uint64_t pk2(float lo, float hi) {
    uint64_t r; asm("mov.b64 %0, {%1, %2};" : "=l"(r) : "f"(lo), "f"(hi)); return r;
}
__device__ __forceinline__ void upk2(uint64_t v, float& lo, float& hi) {
    asm("mov.b64 {%0, %1}, %2;" : "=f"(lo), "=f"(hi) : "l"(v));
}
__device__ __forceinline__ uint64_t fma2(uint64_t a, uint64_t b, uint64_t c) {
    uint64_t d; asm("fma.rn.f32x2 %0, %1, %2, %3;" : "=l"(d) : "l"(a), "l"(b), "l"(c)); return d;
}
__device__ __forceinline__ uint64_t mul2(uint64_t a, uint64_t b) {
    uint64_t d; asm("mul.rn.f32x2 %0, %1, %2;" : "=l"(d) : "l"(a), "l"(b)); return d;
}

// =====================================================================
// transpose (fp32 in -> half out): out[C,R] = half(in[R,C]^T)
// =====================================================================
__global__ __launch_bounds__(256) void transpose_h_kernel(
    const float* __restrict__ in, __half* __restrict__ out, int R, int C)
{
    __shared__ float t[32][33];
    int c0 = blockIdx.x * 32, r0 = blockIdx.y * 32;
    int x = threadIdx.x, y = threadIdx.y;
    #pragma unroll
    for (int i = 0; i < 32; i += 8)
        t[y + i][x] = in[(size_t)(r0 + y + i) * C + c0 + x];
    __syncthreads();
    #pragma unroll
    for (int i = 0; i < 32; i += 8)
        out[(size_t)(c0 + y + i) * R + r0 + x] = __float2half(t[x][y + i]);
}

// batched 3-matrix transpose (Wq, Wk, Wv -> slices of g_wqkvt), each DD x DD
__global__ __launch_bounds__(256) void transpose3_h_kernel(
    const float* __restrict__ s0, const float* __restrict__ s1,
    const float* __restrict__ s2, __half* __restrict__ out)
{
    __shared__ float t[32][33];
    const float* in = (blockIdx.z == 0) ? s0 : (blockIdx.z == 1) ? s1 : s2;
    __half* o = out + (size_t)blockIdx.z * DD * DD;
    int c0 = blockIdx.x * 32, r0 = blockIdx.y * 32;
    int x = threadIdx.x, y = threadIdx.y;
    #pragma unroll
    for (int i = 0; i < 32; i += 8)
        t[y + i][x] = in[(size_t)(r0 + y + i) * DD + c0 + x];
    __syncthreads();
    #pragma unroll
    for (int i = 0; i < 32; i += 8)
        o[(size_t)(c0 + y + i) * DD + r0 + x] = __float2half(t[x][y + i]);
}

// =====================================================================
// LayerNorm (fp32 in -> half out): one block (256 thr) per row
// =====================================================================
__global__ __launch_bounds__(256) void layernorm_kernel(
    const float* __restrict__ x, const float* __restrict__ gamma,
    const float* __restrict__ beta, __half* __restrict__ out)
{
    int row = blockIdx.x;
    int tid = threadIdx.x;
    const float* xr = x + (size_t)row * DD;

    float v0 = xr[tid], v1 = xr[tid + 256], v2 = xr[tid + 512];
    float s = v0 + v1 + v2;

    __shared__ float red[8];
    __shared__ float mu_s, rs_s;

    #pragma unroll
    for (int off = 16; off; off >>= 1) s += __shfl_xor_sync(0xffffffffu, s, off);
    if ((tid & 31) == 0) red[tid >> 5] = s;
    __syncthreads();
    if (tid == 0) {
        float t = 0.f;
        #pragma unroll
        for (int i = 0; i < 8; i++) t += red[i];
        mu_s = t * (1.0f / (float)DD);
    }
    __syncthreads();
    float mu = mu_s;
    float d0 = v0 - mu, d1 = v1 - mu, d2 = v2 - mu;
    float q = d0 * d0 + d1 * d1 + d2 * d2;
    #pragma unroll
    for (int off = 16; off; off >>= 1) q += __shfl_xor_sync(0xffffffffu, q, off);
    if ((tid & 31) == 0) red[tid >> 5] = q;
    __syncthreads();
    if (tid == 0) {
        float t = 0.f;
        #pragma unroll
        for (int i = 0; i < 8; i++) t += red[i];
        rs_s = rsqrtf(t * (1.0f / (float)DD) + EPSV);
    }
    __syncthreads();
    float rs = rs_s;
    __half* orow = out + (size_t)row * DD;
    orow[tid]       = __float2half(d0 * rs * gamma[tid]       + beta[tid]);
    orow[tid + 256] = __float2half(d1 * rs * gamma[tid + 256] + beta[tid + 256]);
    orow[tid + 512] = __float2half(d2 * rs * gamma[tid + 512] + beta[tid + 512]);
}

// =====================================================================
// fp16 mma GEMM, cp.async 3-stage pipeline, ldmatrix fragments
//   A: [M,K] HALF row-major ; Bt: [N,K] HALF row-major
//   C: fp32 (or half when OUTH) = alpha*A@B + bias + relu + res
//   block 128x128, K chunks of 32, 8 warps (2x4) of 64x32 warp tiles.
//   SMEM: [128 rows][32 half], 16B-chunk swizzle  c' = c ^ ((row>>1)&3).
// =====================================================================
template<bool BIAS, bool RELU, bool RES, bool QKVS, bool OUTH>
__global__ __launch_bounds__(256, 2) void mma_gemm(
    int M, int N, int K, float alpha,
    const __half* __restrict__ A, const __half* __restrict__ Bt,
    const float* __restrict__ bias, const float* __restrict__ res,
    void* __restrict__ Cv)
{
    __shared__ uint32_t As3[3][2048];   // 8KB per stage
    __shared__ uint32_t Bs3[3][2048];

    const int tid  = threadIdx.x;
    const int lane = tid & 31, wid = tid >> 5;
    const int g = lane >> 2, t4 = lane & 3;
    const int wm = wid & 1, wn = wid >> 1;       // warp grid 2 (m) x 4 (n)
    const int brow = blockIdx.y * 128;
    const int bcol = blockIdx.x * 128;

    // ---- cp.async staging geometry: thread -> (row = tid>>1, 16-half group = tid&1)
    const int sr  = tid >> 1;
    const int sks = tid & 1;
    const int ssw = (sr >> 1) & 3;
    const uint32_t d0 = 64u * sr + 16u * (uint32_t)((2 * sks + 0) ^ ssw);
    const uint32_t d1 = 64u * sr + 16u * (uint32_t)((2 * sks + 1) ^ ssw);
    const uint32_t aSm = smem_u32(As3);
    const uint32_t bSm = smem_u32(Bs3);
    const __half* Ag = A  + (size_t)(brow + sr) * K + sks * 16;
    const __half* Bg = Bt + (size_t)(bcol + sr) * K + sks * 16;

    // ---- ldmatrix per-lane geometry ----
    const int rA  = ((lane >> 3) & 1) * 8 + (lane & 7);
    const int cA  = lane >> 4;
    const int swA = (rA >> 1) & 3;
    const int rB  = ((lane >> 4) & 1) * 8 + (lane & 7);
    const int cB  = (lane >> 3) & 1;
    const int swB = (rB >> 1) & 3;
    const uint32_t aBase = aSm + 64u * rA;
    const uint32_t bBase = bSm + 64u * rB;

    float acc[4][4][4];
    #pragma unroll
    for (int mt = 0; mt < 4; mt++)
        #pragma unroll
        for (int nt = 0; nt < 4; nt++)
            #pragma unroll
            for (int r = 0; r < 4; r++) acc[mt][nt][r] = 0.f;

    const int nc = K >> 5;

    // prologue: stage chunks 0 and 1
    #pragma unroll
    for (int p = 0; p < 2; p++) {
        const uint32_t so = (uint32_t)p * 8192u;
        cp16(aSm + so + d0, Ag + p * 32);
        cp16(aSm + so + d1, Ag + p * 32 + 8);
        cp16(bSm + so + d0, Bg + p * 32);
        cp16(bSm + so + d1, Bg + p * 32 + 8);
        CP_COMMIT();
    }

    int sbuf = 0;
    for (int ch = 0; ch < nc; ch++) {
        CP_WAIT1();
        __syncthreads();

        // ---- MMA over chunk ch from stage sbuf ----
        const uint32_t aS = aBase + (uint32_t)sbuf * 8192u;
        const uint32_t bS = bBase + (uint32_t)sbuf * 8192u;
        #pragma unroll
        for (int ks = 0; ks < 2; ks++) {
            uint32_t af[4][4], bf[2][4];
            const uint32_t aCh = 16u * (uint32_t)((2 * ks + cA) ^ swA);
            const uint32_t bCh = 16u * (uint32_t)((2 * ks + cB) ^ swB);
            #pragma unroll
            for (int mt = 0; mt < 4; mt++)
                ldsm4(af[mt], aS + 1024u * (uint32_t)(wm * 4 + mt) + aCh);
            #pragma unroll
            for (int jj = 0; jj < 2; jj++)
                ldsm4(bf[jj], bS + 1024u * (uint32_t)(wn * 2 + jj) + bCh);
            #pragma unroll
            for (int mt = 0; mt < 4; mt++)
                #pragma unroll
                for (int nt = 0; nt < 4; nt++)
                    mma16(acc[mt][nt], af[mt], &bf[nt >> 1][(nt & 1) * 2]);
        }

        // issue chunk ch+2 into the stage being vacated next
        if (ch + 2 < nc) {
            const int ns = (ch + 2) % 3;
            const uint32_t so = (uint32_t)ns * 8192u;
            const int k0 = (ch + 2) * 32;
            cp16(aSm + so + d0, Ag + k0);
            cp16(aSm + so + d1, Ag + k0 + 8);
            cp16(bSm + so + d0, Bg + k0);
            cp16(bSm + so + d1, Bg + k0 + 8);
        }
        CP_COMMIT();
        sbuf = (sbuf + 1 == 3) ? 0 : sbuf + 1;
    }

    // ---- epilogue ----
    const float aeff = QKVS ? ((bcol < DD) ? alpha : 1.0f) : alpha;
    float*  Cf = (float*)Cv;
    __half* Ch = (__half*)Cv;
    #pragma unroll
    for (int mt = 0; mt < 4; mt++) {
        const int row0 = brow + wm * 64 + mt * 16 + g;
        const int row1 = row0 + 8;
        #pragma unroll
        for (int nt = 0; nt < 4; nt++) {
            const int col = bcol + wn * 32 + nt * 8 + t4 * 2;
            float2 lo, hi;
            lo.x = acc[mt][nt][0] * aeff; lo.y = acc[mt][nt][1] * aeff;
            hi.x = acc[mt][nt][2] * aeff; hi.y = acc[mt][nt][3] * aeff;
            if (BIAS) {
                const float2 bb = *(const float2*)&bias[col];
                lo.x += bb.x; lo.y += bb.y; hi.x += bb.x; hi.y += bb.y;
            }
            if (RELU) {
                lo.x = fmaxf(lo.x, 0.f); lo.y = fmaxf(lo.y, 0.f);
                hi.x = fmaxf(hi.x, 0.f); hi.y = fmaxf(hi.y, 0.f);
            }
            if (RES) {
                const float2 r0 = *(const float2*)&res[(size_t)row0 * N + col];
                const float2 r1 = *(const float2*)&res[(size_t)row1 * N + col];
                lo.x += r0.x; lo.y += r0.y; hi.x += r1.x; hi.y += r1.y;
            }
            if (OUTH) {
                __half2 hl = __floats2half2_rn(lo.x, lo.y);
                __half2 hh = __floats2half2_rn(hi.x, hi.y);
                *(__half2*)&Ch[(size_t)row0 * N + col] = hl;
                *(__half2*)&Ch[(size_t)row1 * N + col] = hh;
            } else {
                *(float2*)&Cf[(size_t)row0 * N + col] = lo;
                *(float2*)&Cf[(size_t)row1 * N + col] = hi;
            }
        }
    }
}

// =====================================================================
// BigBird flash attention (exact fp32 math, packed f32x2 FMA)
//   grid (NB=64, H=12, B=2), 256 threads (8 warps), warp w owns rows w+8i.
//   Register-blocked: K and V chunks held in regs, reused across 8 rows.
//   Writes ctx as HALF (feeds Wo GEMM).
// =====================================================================
struct PlanT { int v[(NBB - 2) * 8]; };

__global__ __launch_bounds__(256) void attn_kernel(
    const float* __restrict__ q, const float* __restrict__ k,
    const float* __restrict__ v, const PlanT plan,
    __half* __restrict__ ctx)
{
    __shared__ float Qs[64 * 64];   // 16 KB
    __shared__ float Ks[32 * 68];   // padded rows (17 float4) -> conflict-free
    __shared__ float Vs[32 * 64];
    __shared__ float Ps[64 * 33];

    const int qb = blockIdx.x, h = blockIdx.y, b = blockIdx.z;
    const int tid = threadIdx.x;
    const int w = tid >> 5, lane = tid & 31;

    // load Q tile (pre-scaled by 1/sqrt(HD) in the fused QKV GEMM)
    const size_t qbase = ((size_t)(b * LL + qb * 64)) * QKVD + h * HDD;
    #pragma unroll
    for (int i = 0; i < 4; i++) {
        int f = tid + i * 256;
        int r = f >> 4, d4 = (f & 15) * 4;
        *(float4*)&Qs[r * 64 + d4] = *(const float4*)&q[qbase + (size_t)r * QKVD + d4];
    }

    float mreg[8], lreg[8];
    uint64_t od[8];                       // packed (o[lane], o[lane+32]) per row
    const uint64_t z2 = pk2(0.f, 0.f);
    #pragma unroll
    for (int i = 0; i < 8; i++) { mreg[i] = -1e30f; lreg[i] = 0.f; od[i] = z2; }

    const int nkb = (qb == 0 || qb == NBB - 1) ? NBB : 8;

    for (int kbi = 0; kbi < nkb; kbi++) {
        int kb = (nkb == NBB) ? kbi : plan.v[(qb - 1) * 8 + kbi];
        for (int half = 0; half < 2; half++) {
            __syncthreads();   // protect Ks/Vs (and first-iter Qs) from prior readers
            const size_t kbase = ((size_t)(b * LL + kb * 64 + half * 32)) * QKVD + h * HDD;
            #pragma unroll
            for (int i = 0; i < 2; i++) {
                int f = tid + i * 256;
                int c = f >> 4, d4 = (f & 15) * 4;
                *(float4*)&Ks[c * 68 + d4] = *(const float4*)&k[kbase + (size_t)c * QKVD + d4];
                *(float4*)&Vs[c * 64 + d4] = *(const float4*)&v[kbase + (size_t)c * QKVD + d4];
            }
            __syncthreads();

            // ---- QK^T: lane = key, K chunk in regs reused across 8 rows ----
            uint64_t ps[8];
            #pragma unroll
            for (int i = 0; i < 8; i++) ps[i] = z2;
            #pragma unroll
            for (int dc = 0; dc < 4; dc++) {
                const float4* kr = (const float4*)&Ks[lane * 68 + dc * 16];
                float4 k0 = kr[0], k1 = kr[1], k2 = kr[2], k3 = kr[3];
                uint64_t kp0 = pk2(k0.x, k0.y), kp1 = pk2(k0.z, k0.w);
                uint64_t kp2 = pk2(k1.x, k1.y), kp3 = pk2(k1.z, k1.w);
                uint64_t kp4 = pk2(k2.x, k2.y), kp5 = pk2(k2.z, k2.w);
                uint64_t kp6 = pk2(k3.x, k3.y), kp7 = pk2(k3.z, k3.w);
                #pragma unroll
                for (int i = 0; i < 8; i++) {
                    const int r = w + i * 8;
                    const float4* qr = (const float4*)&Qs[r * 64 + dc * 16];
                    float4 q0 = qr[0], q1 = qr[1], q2 = qr[2], q3 = qr[3];
                    ps[i] = fma2(pk2(q0.x, q0.y), kp0, ps[i]);
                    ps[i] = fma2(pk2(q0.z, q0.w), kp1, ps[i]);
                    ps[i] = fma2(pk2(q1.x, q1.y), kp2, ps[i]);
                    ps[i] = fma2(pk2(q1.z, q1.w), kp3, ps[i]);
                    ps[i] = fma2(pk2(q2.x, q2.y), kp4, ps[i]);
                    ps[i] = fma2(pk2(q2.z, q2.w), kp5, ps[i]);
                    ps[i] = fma2(pk2(q3.x, q3.y), kp6, ps[i]);
                    ps[i] = fma2(pk2(q3.z, q3.w), kp7, ps[i]);
                }
            }

            // ---- online softmax per row ----
            #pragma unroll
            for (int i = 0; i < 8; i++) {
                const int r = w + i * 8;
                float slo, shi;
                upk2(ps[i], slo, shi);
                float s = slo + shi;
                float cm = s;
                #pragma unroll
                for (int off = 16; off; off >>= 1)
                    cm = fmaxf(cm, __shfl_xor_sync(0xffffffffu, cm, off));
                float mn = fmaxf(mreg[i], cm);
                float sc = __expf(mreg[i] - mn);
                float p  = __expf(s - mn);
                float pssum = p;
                #pragma unroll
                for (int off = 16; off; off >>= 1)
                    pssum += __shfl_xor_sync(0xffffffffu, pssum, off);
                lreg[i] = lreg[i] * sc + pssum;
                mreg[i] = mn;
                od[i] = mul2(od[i], pk2(sc, sc));
                Ps[r * 33 + lane] = p;
            }
            __syncwarp();

            // ---- P @ V: lane owns dims (lane, lane+32); V chunk in regs ----
            #pragma unroll
            for (int cg = 0; cg < 4; cg++) {
                uint64_t vp[8];
                #pragma unroll
                for (int j = 0; j < 8; j++) {
                    const int c = cg * 8 + j;
                    vp[j] = pk2(Vs[c * 64 + lane], Vs[c * 64 + lane + 32]);
                }
                #pragma unroll
                for (int i = 0; i < 8; i++) {
                    const int r = w + i * 8;
                    const float* pr = &Ps[r * 33 + cg * 8];
                    #pragma unroll
                    for (int j = 0; j < 8; j++) {
                        float p = pr[j];
                        od[i] = fma2(pk2(p, p), vp[j], od[i]);
                    }
                }
            }
        }
    }

    // write context as HALF in [B*L, D] layout (col = h*64 + d)
    const size_t obase = ((size_t)(b * LL + qb * 64)) * DD + h * HDD;
    #pragma unroll
    for (int i = 0; i < 8; i++) {
        const int r = w + i * 8;
        float inv = 1.0f / lreg[i];
        float o0, o1;
        upk2(od[i], o0, o1);
        ctx[obase + (size_t)r * DD + lane]      = __float2half(o0 * inv);
        ctx[obase + (size_t)r * DD + lane + 32] = __float2half(o1 * inv);
    }
}

// =====================================================================
// host-side numpy MT19937 (legacy RandomState(0)) -> BigBird plan
// =====================================================================
namespace hostmt {
struct MT {
    unsigned int key[624];
    int pos;
};
static void mt_seed(MT& s, unsigned int seed) {
    for (int p = 0; p < 624; p++) {
        s.key[p] = seed;
        seed = 1812433253u * (seed ^ (seed >> 30)) + (unsigned)p + 1u;
    }
    s.pos = 624;
}
static unsigned int mt_next(MT& s) {
    if (s.pos == 624) {
        for (int i = 0; i < 624; i++) {
            unsigned int y = (s.key[i] & 0x80000000u) | (s.key[(i + 1) % 624] & 0x7fffffffu);
            s.key[i] = s.key[(i + 397) % 624] ^ (y >> 1) ^ ((y & 1u) ? 0x9908b0dfu : 0u);
        }
        s.pos = 0;
    }
    unsigned int y = s.key[s.pos++];
    y ^= y >> 11;
    y ^= (y << 7)  & 0x9d2c5680u;
    y ^= (y << 15) & 0xefc60000u;
    y ^= y >> 18;
    return y;
}
static unsigned int mt_interval(MT& s, unsigned int mx) {
    if (mx == 0u) return 0u;
    unsigned int mask = mx;
    mask |= mask >> 1; mask |= mask >> 2; mask |= mask >> 4;
    mask |= mask >> 8; mask |= mask >> 16;
    unsigned int v;
    while ((v = (mt_next(s) & mask)) > mx) { }
    return v;
}
static void make_plan(int* plan) {
    MT st;
    mt_seed(st, 0u);
    for (int i = 1; i <= NBB - 2; i++) {
        int cand[64]; int n = 0;
        for (int j = 0; j < NBB; j++) {
            if (j == 0 || j == NBB - 1 || j == i - 1 || j == i || j == i + 1) continue;
            cand[n++] = j;
        }
        int perm[64];
        for (int j = 0; j < n; j++) perm[j] = j;
        for (int ii = n - 1; ii >= 1; ii--) {
            int j = (int)mt_interval(st, (unsigned)ii);
            int t = perm[ii]; perm[ii] = perm[j]; perm[j] = t;
        }
        int* row = plan + (i - 1) * 8;
        row[0] = 0; row[1] = NBB - 1; row[2] = i - 1; row[3] = i; row[4] = i + 1;
        for (int t = 0; t < 3; t++) row[5 + t] = cand[perm[t]];
    }
}
} // namespace hostmt

// =====================================================================
// launch
// =====================================================================
extern "C" void kernel_launch(void* const* d_in, const int* in_sizes, int n_in,
                              void* d_out, int out_size)
{
    (void)in_sizes; (void)n_in; (void)out_size;
    const float* x    = (const float*)d_in[0];
    const float* ln1s = (const float*)d_in[1];
    const float* ln1b = (const float*)d_in[2];
    const float* Wq   = (const float*)d_in[3];   // [D, H*HD] flat
    const float* Wk   = (const float*)d_in[4];
    const float* Wv   = (const float*)d_in[5];
    const float* Wo   = (const float*)d_in[6];   // [H*HD, D] flat
    const float* ln2s = (const float*)d_in[7];
    const float* ln2b = (const float*)d_in[8];
    const float* W1   = (const float*)d_in[9];   // [D, MLP]
    const float* b1   = (const float*)d_in[10];
    const float* W2   = (const float*)d_in[11];  // [MLP, D]
    const float* b2   = (const float*)d_in[12];
    float* out = (float*)d_out;

    void *ph, *pqkv, *pctx, *px1, *py, *pz;
    void *pwqkvt, *pwot, *pw1t, *pw2t;
    cudaGetSymbolAddress(&ph,    g_h);
    cudaGetSymbolAddress(&pqkv,  g_qkv);
    cudaGetSymbolAddress(&pctx,  g_ctx);
    cudaGetSymbolAddress(&px1,   g_x1);
    cudaGetSymbolAddress(&py,    g_y);
    cudaGetSymbolAddress(&pz,    g_z);
    cudaGetSymbolAddress(&pwqkvt, g_wqkvt);
    cudaGetSymbolAddress(&pwot,  g_wot);
    cudaGetSymbolAddress(&pw1t,  g_w1t);
    cudaGetSymbolAddress(&pw2t,  g_w2t);

    __half* fh    = (__half*)ph;
    float*  fqkv  = (float*)pqkv;
    __half* fctx  = (__half*)pctx;
    float*  fx1   = (float*)px1;
    __half* fy    = (__half*)py;
    __half* fz    = (__half*)pz;
    __half* wqkvt = (__half*)pwqkvt;
    __half* wot   = (__half*)pwot;
    __half* w1t   = (__half*)pw1t;
    __half* w2t   = (__half*)pw2t;

    // host-computed BigBird plan (numpy MT19937 replica) as kernel param
    PlanT plan;
    hostmt::make_plan(plan.v);

    dim3 tb(32, 8);

    // #1-#3 (ncu captures my 4th launch -> make it the attention kernel)
    transpose3_h_kernel<<<dim3(DD / 32, DD / 32, 3), tb>>>(Wq, Wk, Wv, wqkvt);
    layernorm_kernel<<<ROWS, 256>>>(x, ln1s, ln1b, fh);
    dim3 gqkv(QKVD / 128, ROWS / 128);
    mma_gemm<false, false, false, true, false><<<gqkv, 256>>>(ROWS, QKVD, DD, 0.125f, fh, wqkvt, nullptr, nullptr, fqkv);

    // #4: BigBird attention -> ctx (half)  [PROFILED]
    attn_kernel<<<dim3(NBB, HH, BB), 256>>>(fqkv, fqkv + DD, fqkv + 2 * DD, plan, fctx);

    // remaining weight transposes
    transpose_h_kernel<<<dim3(DD / 32, DD / 32), tb>>>(Wo, wot, DD, DD);
    transpose_h_kernel<<<dim3(MLPD / 32, DD / 32), tb>>>(W1, w1t, DD, MLPD);
    transpose_h_kernel<<<dim3(DD / 32, MLPD / 32), tb>>>(W2, w2t, MLPD, DD);

    // x1 = ctx @ Wo + x
    dim3 gdd(DD / 128, ROWS / 128);
    mma_gemm<false, false, true, false, false><<<gdd, 256>>>(ROWS, DD, DD, 1.0f, fctx, wot, nullptr, x, fx1);

    // y = LN2(x1)  (half out)
    layernorm_kernel<<<ROWS, 256>>>(fx1, ln2s, ln2b, fy);

    // z = relu(y @ W1 + b1)  (half out)
    dim3 gm1(MLPD / 128, ROWS / 128);
    mma_gemm<true, true, false, false, true><<<gm1, 256>>>(ROWS, MLPD, DD, 1.0f, fy, w1t, b1, nullptr, fz);

    // out = z @ W2 + b2 + x1
    mma_gemm<true, false, true, false, false><<<gdd, 256>>>(ROWS, DD, MLPD, 1.0f, fz, w2t, b2, fx1, out);
}